// round 16
// baseline (speedup 1.0000x reference)
#include <cuda_runtime.h>
#include <cuda_fp16.h>
#include <stdint.h>
#include <math.h>

#define NBATCH 4
#define SQ    2048
#define SKV   4096
#define EDIM  1024
#define CDIM  512
#define HEADS 16
#define HDIM  64

// ---------------------------------------------------------------------------
// Static device scratch.
// ---------------------------------------------------------------------------
__device__ float  g_cond[(size_t)NBATCH * SQ * EDIM];      // fp32 cond (attn input)
__device__ __half g_ch[(size_t)NBATCH * SQ * CDIM];        // condition fp16
__device__ __half g_wch[(size_t)EDIM * CDIM];              // Wc fp16
__device__ __half g_woh[(size_t)EDIM * EDIM];              // Wo fp16
__device__ __half g_aoh[(size_t)NBATCH * SKV * EDIM];      // attn out fp16

// ---------------------------------------------------------------------------
// PTX helpers
// ---------------------------------------------------------------------------
__device__ __forceinline__ uint32_t smem_u32(const void* p) {
    uint32_t a;
    asm("{ .reg .u64 t; cvta.to.shared.u64 t, %1; cvt.u32.u64 %0, t; }"
        : "=r"(a) : "l"(p));
    return a;
}

__device__ __forceinline__ void cp16(uint32_t dst, const void* src) {
    asm volatile("cp.async.cg.shared.global [%0], [%1], 16;\n" :: "r"(dst), "l"(src));
}

#define LDSM4(r, addr) \
    asm volatile("ldmatrix.sync.aligned.m8n8.x4.shared.b16 {%0,%1,%2,%3}, [%4];" \
        : "=r"((r)[0]), "=r"((r)[1]), "=r"((r)[2]), "=r"((r)[3]) : "r"(addr))

#define LDSM4T(r, addr) \
    asm volatile("ldmatrix.sync.aligned.m8n8.x4.trans.shared.b16 {%0,%1,%2,%3}, [%4];" \
        : "=r"((r)[0]), "=r"((r)[1]), "=r"((r)[2]), "=r"((r)[3]) : "r"(addr))

#define MMA16816(d, a, b) \
    asm volatile("mma.sync.aligned.m16n8k16.row.col.f32.f16.f16.f32 " \
        "{%0,%1,%2,%3}, {%4,%5,%6,%7}, {%8,%9}, {%0,%1,%2,%3};" \
        : "+f"((d)[0]), "+f"((d)[1]), "+f"((d)[2]), "+f"((d)[3]) \
        : "r"((a)[0]), "r"((a)[1]), "r"((a)[2]), "r"((a)[3]), \
          "r"((b)[0]), "r"((b)[1]))

__device__ __forceinline__ uint32_t packh2(float a, float b) {
    __half2 h = __floats2half2_rn(a, b);
    return *(uint32_t*)&h;
}

// ---------------------------------------------------------------------------
// fused convert: fp32 -> fp16 for condition, Wc, Wo in one launch
// ---------------------------------------------------------------------------
#define N_COND (NBATCH * SQ * CDIM)
#define N_WC   (EDIM * CDIM)
#define N_WO   (EDIM * EDIM)

__global__ __launch_bounds__(256) void to_half_all(
    const float* __restrict__ s0, __half* __restrict__ d0,
    const float* __restrict__ s1, __half* __restrict__ d1,
    const float* __restrict__ s2, __half* __restrict__ d2)
{
    int i = (blockIdx.x * blockDim.x + threadIdx.x) * 4;
    const float* src;
    __half* dst;
    if (i < N_COND)                { src = s0;  dst = d0; }
    else if (i < N_COND + N_WC)    { src = s1 - N_COND; dst = d1 - N_COND; }
    else if (i < N_COND + N_WC + N_WO) {
        src = s2 - (N_COND + N_WC); dst = d2 - (N_COND + N_WC);
    } else return;
    float4 v = *(const float4*)(src + i);
    *(__half2*)(dst + i)     = __floats2half2_rn(v.x, v.y);
    *(__half2*)(dst + i + 2) = __floats2half2_rn(v.z, v.w);
}

// ---------------------------------------------------------------------------
// HMMA fp16 GEMM (R13 base; chunk c+2 loads now issued at ks=2 for deeper
// overlap across the chunk boundary).
// ---------------------------------------------------------------------------
#define BM 128
#define BN 128
#define BKC 64
#define AROW 144
#define ASTAGE (128 * AROW)
#define STAGE  (2 * ASTAGE)
#define NSTAGE 3
#define DSMEM  (NSTAGE * STAGE)

__device__ __forceinline__ void gemm_issue(
    uint32_t s0, int slot, int c, int K, int tid, int mBase, int nBase,
    const __half* __restrict__ A, const __half* __restrict__ B)
{
    int k0 = c * BKC;
    uint32_t sA = s0 + slot * STAGE;
    uint32_t sB = sA + ASTAGE;
    #pragma unroll
    for (int i = 0; i < 8; i++) {
        int ch = tid + i * 128;
        int r = ch >> 3, col = ch & 7;
        cp16(sA + r * AROW + col * 16, A + (size_t)(mBase + r) * K + k0 + col * 8);
        cp16(sB + r * AROW + col * 16, B + (size_t)(nBase + r) * K + k0 + col * 8);
    }
    asm volatile("cp.async.commit_group;");
}

__device__ __forceinline__ void load_a(
    uint32_t sA, int ks, int wm, int lane, uint32_t af[4][4])
{
    #pragma unroll
    for (int mi = 0; mi < 4; mi++) {
        uint32_t addr = sA + (wm + mi * 16 + (lane & 15)) * AROW
                      + ks * 32 + (lane >> 4) * 16;
        LDSM4(af[mi], addr);
    }
}

__device__ __forceinline__ void load_b_half(
    uint32_t sB, int ks, int wn, int lane, int h, uint32_t bf[4][2])
{
    #pragma unroll
    for (int p2 = 0; p2 < 2; p2++) {
        int p = h * 2 + p2;
        int grp = lane >> 3, w = lane & 7;
        int nsel = p * 2 + (grp >> 1);
        uint32_t addr = sB + (wn + nsel * 8 + w) * AROW
                      + ks * 32 + (grp & 1) * 16;
        uint32_t r[4];
        LDSM4(r, addr);
        bf[p2 * 2][0]     = r[0];
        bf[p2 * 2][1]     = r[1];
        bf[p2 * 2 + 1][0] = r[2];
        bf[p2 * 2 + 1][1] = r[3];
    }
}

__global__ __launch_bounds__(128, 2) void gemm_hmma(
    const __half* __restrict__ A, const __half* __restrict__ B,
    const float* __restrict__ bias, float* __restrict__ C,
    int M, int N, int K)
{
    extern __shared__ char smem[];
    const int tid  = threadIdx.x;
    const int wid  = tid >> 5;
    const int lane = tid & 31;
    const int mBase = blockIdx.y * BM;
    const int nBase = blockIdx.x * BN;
    const int wm = (wid & 1) * 64;
    const int wn = (wid >> 1) * 64;
    const int rot = (wid & 1) * 2;

    const uint32_t s0 = smem_u32(smem);
    const int NC = K / BKC;

    float acc[4][8][4];
    #pragma unroll
    for (int i = 0; i < 4; i++)
        #pragma unroll
        for (int j = 0; j < 8; j++)
            #pragma unroll
            for (int q = 0; q < 4; q++) acc[i][j][q] = 0.f;

    gemm_issue(s0, 0, 0, K, tid, mBase, nBase, A, B);
    gemm_issue(s0, 1, 1, K, tid, mBase, nBase, A, B);
    asm volatile("cp.async.wait_group 1;");
    __syncthreads();

    uint32_t af[2][4][4];
    load_a(s0, rot, wm, lane, af[0]);

    int buf = 0;
    for (int c = 0; c < NC; c++) {
        uint32_t csA = s0 + (c % NSTAGE) * STAGE;
        uint32_t csB = csA + ASTAGE;
        #pragma unroll
        for (int ksi = 0; ksi < 4; ksi++) {
            const int ksr = (ksi + rot) & 3;
            int nb = buf ^ 1;
            uint32_t bf0[4][2], bf1[4][2];
            load_b_half(csB, ksr, wn, lane, 0, bf0);
            load_b_half(csB, ksr, wn, lane, 1, bf1);

            if (ksi == 2) {
                // issue next-next chunk loads one ks earlier for overlap
                load_a(csA, (ksi + 1 + rot) & 3, wm, lane, af[nb]);
                if (c + 2 < NC)
                    gemm_issue(s0, (c + 2) % NSTAGE, c + 2, K, tid,
                               mBase, nBase, A, B);
                else
                    asm volatile("cp.async.commit_group;");
            } else if (ksi < 2) {
                load_a(csA, (ksi + 1 + rot) & 3, wm, lane, af[nb]);
            } else {        // ksi == 3
                if (c + 1 < NC) {
                    asm volatile("cp.async.wait_group 1;");
                    __syncthreads();
                    uint32_t nA = s0 + ((c + 1) % NSTAGE) * STAGE;
                    load_a(nA, rot, wm, lane, af[nb]);
                }
            }

            #pragma unroll
            for (int mi = 0; mi < 4; mi++)
                #pragma unroll
                for (int ni = 0; ni < 4; ni++)
                    MMA16816(acc[mi][ni], af[buf][mi], bf0[ni]);
            #pragma unroll
            for (int mi = 0; mi < 4; mi++)
                #pragma unroll
                for (int ni = 0; ni < 4; ni++)
                    MMA16816(acc[mi][ni + 4], af[buf][mi], bf1[ni]);

            buf = nb;
        }
    }

    const int g = lane >> 2, tg = lane & 3;
    #pragma unroll
    for (int mi = 0; mi < 4; mi++) {
        int row0 = mBase + wm + mi * 16 + g;
        #pragma unroll
        for (int ni = 0; ni < 8; ni++) {
            int col = nBase + wn + ni * 8 + tg * 2;
            float b0 = __ldg(bias + col), b1 = __ldg(bias + col + 1);
            float2 v0 = make_float2(acc[mi][ni][0] + b0, acc[mi][ni][1] + b1);
            float2 v1 = make_float2(acc[mi][ni][2] + b0, acc[mi][ni][3] + b1);
            *(float2*)(C + (size_t)row0 * N + col) = v0;
            *(float2*)(C + (size_t)(row0 + 8) * N + col) = v1;
        }
    }
}

// ---------------------------------------------------------------------------
// MMA attention, 2 positions computed concurrently by warps 0 and 1.
// 8 positions per CTA in 4 pairs; double-buffered cp.async staging per pair.
// Dynamic smem (72KB > 48KB static limit).
// ---------------------------------------------------------------------------
#define POS_PER_CTA 8
#define HROW 72   // fp16 row stride in halves (144B)

struct AttnStage {
    float4 cq[256];        // [h*16 + dv]
    float4 kv[16 * 17];    // [e*17 + dv]
    float4 vv[16 * 17];    // [e*17 + dv]
    int    msk[256];       // [h*16 + e]
};

struct AttnSmem {
    AttnStage stg[2][2];           // [buffer][posInPair]
    __half cqh[2][16 * HROW];
    __half kh[2][16 * HROW];
    __half vh[2][16 * HROW];
    __half outh[2][1024];
};
#define ATTN_SMEM ((int)sizeof(AttnSmem))

__global__ __launch_bounds__(256) void attn_kernel(
    const float* __restrict__ queries, const float* __restrict__ keys,
    const float* __restrict__ values, const int* __restrict__ mask)
{
    extern __shared__ char asmem_raw[];
    AttnSmem* sm = (AttnSmem*)asmem_raw;

    const int tid = threadIdx.x;
    const int wid = tid >> 5;
    const int lane = tid & 31;
    const int h = tid >> 4;
    const int e = tid & 15;
    const int pos0 = blockIdx.x * POS_PER_CTA;

    const uint32_t smbase = smem_u32(sm);

    // issue loads for pair pr into buffer s (2 positions)
    auto issue = [&](int pr, int s) {
        #pragma unroll
        for (int q = 0; q < 2; q++) {
            const int pos = pos0 + pr * 2 + q;
            const int n = pos >> 12;
            const int t = pos & (SKV - 1);
            const float* cqrow = (t & 1)
                ? (g_cond  + (size_t)(n * SQ + (t >> 1)) * EDIM)
                : (queries + (size_t)(n * SQ + (t >> 1)) * EDIM);
            const float* krow = keys   + (size_t)pos * EDIM;
            const float* vrow = values + (size_t)pos * EDIM;
            const int* mrow = mask + (size_t)pos * (HEADS * HEADS);

            uint32_t sb = smbase
                + (uint32_t)((char*)&sm->stg[s][q] - (char*)sm);
            cp16(sb + (uint32_t)(offsetof(AttnStage, cq)) + tid * 16,
                 cqrow + tid * 4);
            cp16(sb + (uint32_t)(offsetof(AttnStage, kv)) + (h * 17 + e) * 16,
                 krow + tid * 4);
            cp16(sb + (uint32_t)(offsetof(AttnStage, vv)) + (h * 17 + e) * 16,
                 vrow + tid * 4);
            if (tid < 64)
                cp16(sb + (uint32_t)(offsetof(AttnStage, msk)) + tid * 16,
                     mrow + tid * 4);
        }
        asm volatile("cp.async.commit_group;");
    };

    issue(0, 0);

    const int NPAIR = POS_PER_CTA / 2;
    for (int pr = 0; pr < NPAIR; pr++) {
        const int s = pr & 1;
        if (pr + 1 < NPAIR) {
            issue(pr + 1, s ^ 1);
            asm volatile("cp.async.wait_group 1;");
        } else {
            asm volatile("cp.async.wait_group 0;");
        }
        __syncthreads();                 // fp32 pair ready

        // cooperative fp32 -> fp16 convert for both positions
        #pragma unroll
        for (int q = 0; q < 2; q++) {
            const AttnStage& st = sm->stg[s][q];
            float4 qq = st.cq[tid];
            *(uint2*)&sm->cqh[q][h * HROW + e * 4]
                = make_uint2(packh2(qq.x, qq.y), packh2(qq.z, qq.w));
            float4 kk = st.kv[h * 17 + e];
            *(uint2*)&sm->kh[q][h * HROW + e * 4]
                = make_uint2(packh2(kk.x, kk.y), packh2(kk.z, kk.w));
            float4 vv = st.vv[h * 17 + e];
            *(uint2*)&sm->vh[q][h * HROW + e * 4]
                = make_uint2(packh2(vv.x, vv.y), packh2(vv.z, vv.w));
        }
        __syncthreads();                 // fp16 ready

        if (wid < 2) {
            const int q = wid;
            const AttnStage& st = sm->stg[s][q];
            const uint32_t cqh_a = smem_u32(sm->cqh[q]);
            const uint32_t kh_a  = smem_u32(sm->kh[q]);
            const uint32_t vh_a  = smem_u32(sm->vh[q]);

            // scores: C[16x16] = cq(16x64) @ K(16x64)^T
            float C1[4] = {0.f, 0.f, 0.f, 0.f};
            float C2[4] = {0.f, 0.f, 0.f, 0.f};
            #pragma unroll
            for (int ks = 0; ks < 4; ks++) {
                uint32_t a[4], b[4];
                LDSM4(a, cqh_a + (lane & 15) * 144 + ks * 32 + (lane >> 4) * 16);
                LDSM4(b, kh_a + ((lane >> 4) * 8 + (lane & 7)) * 144
                             + ks * 32 + ((lane >> 3) & 1) * 16);
                MMA16816(C1, a, b);
                MMA16816(C2, a, b + 2);
            }

            // softmax in fragment layout
            const int g = lane >> 2, tg = lane & 3;
            float sc[8];
            sc[0] = C1[0]; sc[1] = C1[1]; sc[2] = C1[2]; sc[3] = C1[3];
            sc[4] = C2[0]; sc[5] = C2[1]; sc[6] = C2[2]; sc[7] = C2[3];
            #pragma unroll
            for (int i = 0; i < 8; i++) {
                int row = g + ((i >> 1) & 1) * 8;
                int col = 2 * tg + (i & 1) + (i >= 4 ? 8 : 0);
                float v = sc[i] * 0.125f;
                if (st.msk[row * 16 + col] == 0) v = -1e20f;
                sc[i] = v;
            }
            float mxA = fmaxf(fmaxf(sc[0], sc[1]), fmaxf(sc[4], sc[5]));
            float mxB = fmaxf(fmaxf(sc[2], sc[3]), fmaxf(sc[6], sc[7]));
            #pragma unroll
            for (int m = 1; m < 4; m <<= 1) {
                mxA = fmaxf(mxA, __shfl_xor_sync(0xffffffffu, mxA, m));
                mxB = fmaxf(mxB, __shfl_xor_sync(0xffffffffu, mxB, m));
            }
            float ex[8];
            ex[0] = __expf(sc[0] - mxA); ex[1] = __expf(sc[1] - mxA);
            ex[4] = __expf(sc[4] - mxA); ex[5] = __expf(sc[5] - mxA);
            ex[2] = __expf(sc[2] - mxB); ex[3] = __expf(sc[3] - mxB);
            ex[6] = __expf(sc[6] - mxB); ex[7] = __expf(sc[7] - mxB);
            float dA = ex[0] + ex[1] + ex[4] + ex[5];
            float dB = ex[2] + ex[3] + ex[6] + ex[7];
            #pragma unroll
            for (int m = 1; m < 4; m <<= 1) {
                dA += __shfl_xor_sync(0xffffffffu, dA, m);
                dB += __shfl_xor_sync(0xffffffffu, dB, m);
            }
            float rA = __frcp_rn(dA), rB = __frcp_rn(dB);

            uint32_t pa[4];
            pa[0] = packh2(ex[0] * rA, ex[1] * rA);
            pa[1] = packh2(ex[2] * rB, ex[3] * rB);
            pa[2] = packh2(ex[4] * rA, ex[5] * rA);
            pa[3] = packh2(ex[6] * rB, ex[7] * rB);

            // AV: out(16x64) = P(16x16) @ V(16x64)
            #pragma unroll
            for (int cp2 = 0; cp2 < 4; cp2++) {
                int c = cp2 * 2;
                uint32_t b[4];
                LDSM4T(b, vh_a + (lane & 15) * 144 + (c + (lane >> 4)) * 16);
                float O1[4] = {0.f, 0.f, 0.f, 0.f};
                float O2[4] = {0.f, 0.f, 0.f, 0.f};
                MMA16816(O1, pa, b);
                MMA16816(O2, pa, b + 2);
                __half* oq = sm->outh[q];
                *(__half2*)&oq[g * 64 + c * 8 + 2 * tg]
                    = __floats2half2_rn(O1[0], O1[1]);
                *(__half2*)&oq[(g + 8) * 64 + c * 8 + 2 * tg]
                    = __floats2half2_rn(O1[2], O1[3]);
                *(__half2*)&oq[g * 64 + (c + 1) * 8 + 2 * tg]
                    = __floats2half2_rn(O2[0], O2[1]);
                *(__half2*)&oq[(g + 8) * 64 + (c + 1) * 8 + 2 * tg]
                    = __floats2half2_rn(O2[2], O2[3]);
            }
        }
        __syncthreads();                 // outh ready

        // cooperative coalesced stores for both positions
        #pragma unroll
        for (int q = 0; q < 2; q++) {
            const int pos = pos0 + pr * 2 + q;
            uint2 val = *(uint2*)&sm->outh[q][tid * 4];
            *(uint2*)(g_aoh + (size_t)pos * EDIM + tid * 4) = val;
        }
        __syncthreads();                 // buffer s free
    }
}

// ---------------------------------------------------------------------------
// Launch
// ---------------------------------------------------------------------------
extern "C" void kernel_launch(void* const* d_in, const int* in_sizes, int n_in,
                              void* d_out, int out_size)
{
    const float* values    = (const float*)d_in[0];
    const float* keys      = (const float*)d_in[1];
    const float* queries   = (const float*)d_in[2];
    const int*   mask      = (const int*)  d_in[3];
    const float* condition = (const float*)d_in[4];
    const float* Wc        = (const float*)d_in[5];
    const float* bc        = (const float*)d_in[6];
    const float* Wo        = (const float*)d_in[7];
    const float* bo        = (const float*)d_in[8];
    float* out = (float*)d_out;

    float* cond_ptr;
    __half *ch, *wch, *woh, *aoh;
    cudaGetSymbolAddress((void**)&cond_ptr, g_cond);
    cudaGetSymbolAddress((void**)&ch,  g_ch);
    cudaGetSymbolAddress((void**)&wch, g_wch);
    cudaGetSymbolAddress((void**)&woh, g_woh);
    cudaGetSymbolAddress((void**)&aoh, g_aoh);

    cudaFuncSetAttribute(gemm_hmma,
                         cudaFuncAttributeMaxDynamicSharedMemorySize, DSMEM);
    cudaFuncSetAttribute(attn_kernel,
                         cudaFuncAttributeMaxDynamicSharedMemorySize, ATTN_SMEM);

    // fused converts (one launch)
    {
        int ntot = N_COND + N_WC + N_WO;
        to_half_all<<<ntot / 4 / 256, 256>>>(condition, ch, Wc, wch, Wo, woh);
    }

    // 1) cond = condition @ Wc^T + bc : M=8192, N=1024, K=512
    {
        dim3 grid(EDIM / BN, (NBATCH * SQ) / BM);
        gemm_hmma<<<grid, 128, DSMEM>>>(ch, wch, bc, cond_ptr,
                                        NBATCH * SQ, EDIM, CDIM);
    }

    // 2) attention -> g_aoh (fp16), MMA, 2 positions per pair
    attn_kernel<<<(NBATCH * SKV) / POS_PER_CTA, 256, ATTN_SMEM>>>(
        queries, keys, values, mask);

    // 3) out = attout @ Wo^T + bo : M=16384, N=1024, K=1024
    {
        dim3 grid(EDIM / BN, (NBATCH * SKV) / BM);
        gemm_hmma<<<grid, 128, DSMEM>>>(aoh, woh, bo, out,
                                        NBATCH * SKV, EDIM, EDIM);
    }
}

// round 17
// speedup vs baseline: 1.0257x; 1.0257x over previous
#include <cuda_runtime.h>
#include <cuda_fp16.h>
#include <stdint.h>
#include <math.h>

#define NBATCH 4
#define SQ    2048
#define SKV   4096
#define EDIM  1024
#define CDIM  512
#define HEADS 16
#define HDIM  64

// ---------------------------------------------------------------------------
// Static device scratch.
// ---------------------------------------------------------------------------
__device__ float  g_cond[(size_t)NBATCH * SQ * EDIM];      // fp32 cond (attn input)
__device__ __half g_ch[(size_t)NBATCH * SQ * CDIM];        // condition fp16
__device__ __half g_wch[(size_t)EDIM * CDIM];              // Wc fp16
__device__ __half g_woh[(size_t)EDIM * EDIM];              // Wo fp16
__device__ __half g_aoh[(size_t)NBATCH * SKV * EDIM];      // attn out fp16

// ---------------------------------------------------------------------------
// PTX helpers
// ---------------------------------------------------------------------------
__device__ __forceinline__ uint32_t smem_u32(const void* p) {
    uint32_t a;
    asm("{ .reg .u64 t; cvta.to.shared.u64 t, %1; cvt.u32.u64 %0, t; }"
        : "=r"(a) : "l"(p));
    return a;
}

__device__ __forceinline__ void cp16(uint32_t dst, const void* src) {
    asm volatile("cp.async.cg.shared.global [%0], [%1], 16;\n" :: "r"(dst), "l"(src));
}

#define LDSM4(r, addr) \
    asm volatile("ldmatrix.sync.aligned.m8n8.x4.shared.b16 {%0,%1,%2,%3}, [%4];" \
        : "=r"((r)[0]), "=r"((r)[1]), "=r"((r)[2]), "=r"((r)[3]) : "r"(addr))

#define LDSM4T(r, addr) \
    asm volatile("ldmatrix.sync.aligned.m8n8.x4.trans.shared.b16 {%0,%1,%2,%3}, [%4];" \
        : "=r"((r)[0]), "=r"((r)[1]), "=r"((r)[2]), "=r"((r)[3]) : "r"(addr))

#define MMA16816(d, a, b) \
    asm volatile("mma.sync.aligned.m16n8k16.row.col.f32.f16.f16.f32 " \
        "{%0,%1,%2,%3}, {%4,%5,%6,%7}, {%8,%9}, {%0,%1,%2,%3};" \
        : "+f"((d)[0]), "+f"((d)[1]), "+f"((d)[2]), "+f"((d)[3]) \
        : "r"((a)[0]), "r"((a)[1]), "r"((a)[2]), "r"((a)[3]), \
          "r"((b)[0]), "r"((b)[1]))

__device__ __forceinline__ uint32_t packh2(float a, float b) {
    __half2 h = __floats2half2_rn(a, b);
    return *(uint32_t*)&h;
}

// ---------------------------------------------------------------------------
// fused convert: fp32 -> fp16 for condition, Wc, Wo in one launch
// ---------------------------------------------------------------------------
#define N_COND (NBATCH * SQ * CDIM)
#define N_WC   (EDIM * CDIM)
#define N_WO   (EDIM * EDIM)

__global__ __launch_bounds__(256) void to_half_all(
    const float* __restrict__ s0, __half* __restrict__ d0,
    const float* __restrict__ s1, __half* __restrict__ d1,
    const float* __restrict__ s2, __half* __restrict__ d2)
{
    int i = (blockIdx.x * blockDim.x + threadIdx.x) * 4;
    const float* src;
    __half* dst;
    if (i < N_COND)                { src = s0;  dst = d0; }
    else if (i < N_COND + N_WC)    { src = s1 - N_COND; dst = d1 - N_COND; }
    else if (i < N_COND + N_WC + N_WO) {
        src = s2 - (N_COND + N_WC); dst = d2 - (N_COND + N_WC);
    } else return;
    float4 v = *(const float4*)(src + i);
    *(__half2*)(dst + i)     = __floats2half2_rn(v.x, v.y);
    *(__half2*)(dst + i + 2) = __floats2half2_rn(v.z, v.w);
}

// ---------------------------------------------------------------------------
// HMMA fp16 GEMM. R15 schedule + FULL operand double-buffering: A-frags and
// both B halves for ks+1 prefetched during ks's MMA burst. One exposed LDSM
// chain per chunk (after the boundary sync) instead of per ks.
// ---------------------------------------------------------------------------
#define BM 128
#define BN 128
#define BKC 64
#define AROW 144
#define ASTAGE (128 * AROW)
#define STAGE  (2 * ASTAGE)
#define NSTAGE 3
#define DSMEM  (NSTAGE * STAGE)

__device__ __forceinline__ void gemm_issue(
    uint32_t s0, int slot, int c, int K, int tid, int mBase, int nBase,
    const __half* __restrict__ A, const __half* __restrict__ B)
{
    int k0 = c * BKC;
    uint32_t sA = s0 + slot * STAGE;
    uint32_t sB = sA + ASTAGE;
    #pragma unroll
    for (int i = 0; i < 8; i++) {
        int ch = tid + i * 128;
        int r = ch >> 3, col = ch & 7;
        cp16(sA + r * AROW + col * 16, A + (size_t)(mBase + r) * K + k0 + col * 8);
        cp16(sB + r * AROW + col * 16, B + (size_t)(nBase + r) * K + k0 + col * 8);
    }
    asm volatile("cp.async.commit_group;");
}

__device__ __forceinline__ void load_a(
    uint32_t sA, int ks, int wm, int lane, uint32_t af[4][4])
{
    #pragma unroll
    for (int mi = 0; mi < 4; mi++) {
        uint32_t addr = sA + (wm + mi * 16 + (lane & 15)) * AROW
                      + ks * 32 + (lane >> 4) * 16;
        LDSM4(af[mi], addr);
    }
}

__device__ __forceinline__ void load_b_half(
    uint32_t sB, int ks, int wn, int lane, int h, uint32_t bf[4][2])
{
    #pragma unroll
    for (int p2 = 0; p2 < 2; p2++) {
        int p = h * 2 + p2;
        int grp = lane >> 3, w = lane & 7;
        int nsel = p * 2 + (grp >> 1);
        uint32_t addr = sB + (wn + nsel * 8 + w) * AROW
                      + ks * 32 + (grp & 1) * 16;
        uint32_t r[4];
        LDSM4(r, addr);
        bf[p2 * 2][0]     = r[0];
        bf[p2 * 2][1]     = r[1];
        bf[p2 * 2 + 1][0] = r[2];
        bf[p2 * 2 + 1][1] = r[3];
    }
}

__global__ __launch_bounds__(128, 2) void gemm_hmma(
    const __half* __restrict__ A, const __half* __restrict__ B,
    const float* __restrict__ bias, float* __restrict__ C,
    int M, int N, int K)
{
    extern __shared__ char smem[];
    const int tid  = threadIdx.x;
    const int wid  = tid >> 5;
    const int lane = tid & 31;
    const int mBase = blockIdx.y * BM;
    const int nBase = blockIdx.x * BN;
    const int wm = (wid & 1) * 64;
    const int wn = (wid >> 1) * 64;
    const int rot = (wid & 1) * 2;

    const uint32_t s0 = smem_u32(smem);
    const int NC = K / BKC;

    float acc[4][8][4];
    #pragma unroll
    for (int i = 0; i < 4; i++)
        #pragma unroll
        for (int j = 0; j < 8; j++)
            #pragma unroll
            for (int q = 0; q < 4; q++) acc[i][j][q] = 0.f;

    gemm_issue(s0, 0, 0, K, tid, mBase, nBase, A, B);
    gemm_issue(s0, 1, 1, K, tid, mBase, nBase, A, B);
    asm volatile("cp.async.wait_group 1;");
    __syncthreads();

    uint32_t af[2][4][4];
    uint32_t bf0[2][4][2], bf1[2][4][2];
    load_a(s0, rot, wm, lane, af[0]);
    load_b_half(s0 + ASTAGE, rot, wn, lane, 0, bf0[0]);
    load_b_half(s0 + ASTAGE, rot, wn, lane, 1, bf1[0]);

    int buf = 0;
    for (int c = 0; c < NC; c++) {
        uint32_t csA = s0 + (c % NSTAGE) * STAGE;
        uint32_t csB = csA + ASTAGE;
        #pragma unroll
        for (int ksi = 0; ksi < 4; ksi++) {
            int nb = buf ^ 1;
            if (ksi < 3) {
                int nk = (ksi + 1 + rot) & 3;
                load_b_half(csB, nk, wn, lane, 0, bf0[nb]);
                load_b_half(csB, nk, wn, lane, 1, bf1[nb]);
                load_a(csA, nk, wm, lane, af[nb]);
            } else {
                if (c + 2 < NC)
                    gemm_issue(s0, (c + 2) % NSTAGE, c + 2, K, tid,
                               mBase, nBase, A, B);
                else
                    asm volatile("cp.async.commit_group;");
                if (c + 1 < NC) {
                    asm volatile("cp.async.wait_group 1;");
                    __syncthreads();
                    uint32_t nA = s0 + ((c + 1) % NSTAGE) * STAGE;
                    load_b_half(nA + ASTAGE, rot, wn, lane, 0, bf0[nb]);
                    load_b_half(nA + ASTAGE, rot, wn, lane, 1, bf1[nb]);
                    load_a(nA, rot, wm, lane, af[nb]);
                }
            }

            #pragma unroll
            for (int mi = 0; mi < 4; mi++)
                #pragma unroll
                for (int ni = 0; ni < 4; ni++)
                    MMA16816(acc[mi][ni], af[buf][mi], bf0[buf][ni]);
            #pragma unroll
            for (int mi = 0; mi < 4; mi++)
                #pragma unroll
                for (int ni = 0; ni < 4; ni++)
                    MMA16816(acc[mi][ni + 4], af[buf][mi], bf1[buf][ni]);

            buf = nb;
        }
    }

    const int g = lane >> 2, tg = lane & 3;
    #pragma unroll
    for (int mi = 0; mi < 4; mi++) {
        int row0 = mBase + wm + mi * 16 + g;
        #pragma unroll
        for (int ni = 0; ni < 8; ni++) {
            int col = nBase + wn + ni * 8 + tg * 2;
            float b0 = __ldg(bias + col), b1 = __ldg(bias + col + 1);
            float2 v0 = make_float2(acc[mi][ni][0] + b0, acc[mi][ni][1] + b1);
            float2 v1 = make_float2(acc[mi][ni][2] + b0, acc[mi][ni][3] + b1);
            *(float2*)(C + (size_t)row0 * N + col) = v0;
            *(float2*)(C + (size_t)(row0 + 8) * N + col) = v1;
        }
    }
}

// ---------------------------------------------------------------------------
// MMA attention (R15 version, the 176.6us config): pipelined fp32 staging,
// per position cooperative fp32->fp16 convert, warp 0 computes the position
// with 16 HMMAs, softmax in fragment layout.
// ---------------------------------------------------------------------------
#define POS_PER_CTA 8
#define HROW 72   // fp16 row stride in halves (144B)

struct AttnStage {
    float4 cq[256];        // [h*16 + dv]
    float4 kv[16 * 17];    // [e*17 + dv]
    float4 vv[16 * 17];    // [e*17 + dv]
    int    msk[256];       // [h*16 + e]
};

__global__ __launch_bounds__(256) void attn_kernel(
    const float* __restrict__ queries, const float* __restrict__ keys,
    const float* __restrict__ values, const int* __restrict__ mask)
{
    __shared__ AttnStage stg[2];
    __shared__ __half cqh[16 * HROW];
    __shared__ __half kh[16 * HROW];
    __shared__ __half vh[16 * HROW];
    __shared__ __half outh[1024];

    const int tid = threadIdx.x;
    const int wid = tid >> 5;
    const int lane = tid & 31;
    const int h = tid >> 4;
    const int e = tid & 15;
    const int pos0 = blockIdx.x * POS_PER_CTA;

    const uint32_t sbase = smem_u32(&stg[0]);
    const uint32_t stgsz = (uint32_t)sizeof(AttnStage);
    const uint32_t cqh_a = smem_u32(cqh);
    const uint32_t kh_a  = smem_u32(kh);
    const uint32_t vh_a  = smem_u32(vh);

    auto issue = [&](int p, int s) {
        const int pos = pos0 + p;
        const int n = pos >> 12;
        const int t = pos & (SKV - 1);
        const float* cqrow = (t & 1)
            ? (g_cond  + (size_t)(n * SQ + (t >> 1)) * EDIM)
            : (queries + (size_t)(n * SQ + (t >> 1)) * EDIM);
        const float* krow = keys   + (size_t)pos * EDIM;
        const float* vrow = values + (size_t)pos * EDIM;
        const int* mrow = mask + (size_t)pos * (HEADS * HEADS);

        uint32_t sb = sbase + s * stgsz;
        cp16(sb + (uint32_t)(offsetof(AttnStage, cq)) + tid * 16, cqrow + tid * 4);
        cp16(sb + (uint32_t)(offsetof(AttnStage, kv)) + (h * 17 + e) * 16, krow + tid * 4);
        cp16(sb + (uint32_t)(offsetof(AttnStage, vv)) + (h * 17 + e) * 16, vrow + tid * 4);
        if (tid < 64)
            cp16(sb + (uint32_t)(offsetof(AttnStage, msk)) + tid * 16, mrow + tid * 4);
        asm volatile("cp.async.commit_group;");
    };

    issue(0, 0);

    for (int p = 0; p < POS_PER_CTA; p++) {
        const int s = p & 1;
        if (p + 1 < POS_PER_CTA) {
            issue(p + 1, s ^ 1);
            asm volatile("cp.async.wait_group 1;");
        } else {
            asm volatile("cp.async.wait_group 0;");
        }
        __syncthreads();                     // fp32 stage s ready

        const AttnStage& st = stg[s];
        const int pos = pos0 + p;

        // cooperative fp32 -> fp16 convert into 144B-stride rows
        {
            float4 q = st.cq[tid];
            *(uint2*)&cqh[h * HROW + e * 4]
                = make_uint2(packh2(q.x, q.y), packh2(q.z, q.w));
            float4 k = st.kv[h * 17 + e];
            *(uint2*)&kh[h * HROW + e * 4]
                = make_uint2(packh2(k.x, k.y), packh2(k.z, k.w));
            float4 v = st.vv[h * 17 + e];
            *(uint2*)&vh[h * HROW + e * 4]
                = make_uint2(packh2(v.x, v.y), packh2(v.z, v.w));
        }
        __syncthreads();                     // fp16 ready

        if (wid == 0) {
            // scores: C[16x16] = cq(16x64) @ K(16x64)^T
            float C1[4] = {0.f, 0.f, 0.f, 0.f};
            float C2[4] = {0.f, 0.f, 0.f, 0.f};
            #pragma unroll
            for (int ks = 0; ks < 4; ks++) {
                uint32_t a[4], b[4];
                LDSM4(a, cqh_a + (lane & 15) * 144 + ks * 32 + (lane >> 4) * 16);
                LDSM4(b, kh_a + ((lane >> 4) * 8 + (lane & 7)) * 144
                             + ks * 32 + ((lane >> 3) & 1) * 16);
                MMA16816(C1, a, b);
                MMA16816(C2, a, b + 2);
            }

            // softmax in fragment layout
            const int g = lane >> 2, tg = lane & 3;
            float sc[8];
            sc[0] = C1[0]; sc[1] = C1[1]; sc[2] = C1[2]; sc[3] = C1[3];
            sc[4] = C2[0]; sc[5] = C2[1]; sc[6] = C2[2]; sc[7] = C2[3];
            #pragma unroll
            for (int i = 0; i < 8; i++) {
                int row = g + ((i >> 1) & 1) * 8;
                int col = 2 * tg + (i & 1) + (i >= 4 ? 8 : 0);
                float v = sc[i] * 0.125f;
                if (st.msk[row * 16 + col] == 0) v = -1e20f;
                sc[i] = v;
            }
            float mxA = fmaxf(fmaxf(sc[0], sc[1]), fmaxf(sc[4], sc[5]));
            float mxB = fmaxf(fmaxf(sc[2], sc[3]), fmaxf(sc[6], sc[7]));
            #pragma unroll
            for (int m = 1; m < 4; m <<= 1) {
                mxA = fmaxf(mxA, __shfl_xor_sync(0xffffffffu, mxA, m));
                mxB = fmaxf(mxB, __shfl_xor_sync(0xffffffffu, mxB, m));
            }
            float ex[8];
            ex[0] = __expf(sc[0] - mxA); ex[1] = __expf(sc[1] - mxA);
            ex[4] = __expf(sc[4] - mxA); ex[5] = __expf(sc[5] - mxA);
            ex[2] = __expf(sc[2] - mxB); ex[3] = __expf(sc[3] - mxB);
            ex[6] = __expf(sc[6] - mxB); ex[7] = __expf(sc[7] - mxB);
            float dA = ex[0] + ex[1] + ex[4] + ex[5];
            float dB = ex[2] + ex[3] + ex[6] + ex[7];
            #pragma unroll
            for (int m = 1; m < 4; m <<= 1) {
                dA += __shfl_xor_sync(0xffffffffu, dA, m);
                dB += __shfl_xor_sync(0xffffffffu, dB, m);
            }
            float rA = __frcp_rn(dA), rB = __frcp_rn(dB);

            uint32_t pa[4];
            pa[0] = packh2(ex[0] * rA, ex[1] * rA);
            pa[1] = packh2(ex[2] * rB, ex[3] * rB);
            pa[2] = packh2(ex[4] * rA, ex[5] * rA);
            pa[3] = packh2(ex[6] * rB, ex[7] * rB);

            // AV: out(16x64) = P(16x16) @ V(16x64)
            #pragma unroll
            for (int cp2 = 0; cp2 < 4; cp2++) {
                int c = cp2 * 2;
                uint32_t b[4];
                LDSM4T(b, vh_a + (lane & 15) * 144 + (c + (lane >> 4)) * 16);
                float O1[4] = {0.f, 0.f, 0.f, 0.f};
                float O2[4] = {0.f, 0.f, 0.f, 0.f};
                MMA16816(O1, pa, b);
                MMA16816(O2, pa, b + 2);
                *(__half2*)&outh[g * 64 + c * 8 + 2 * tg]
                    = __floats2half2_rn(O1[0], O1[1]);
                *(__half2*)&outh[(g + 8) * 64 + c * 8 + 2 * tg]
                    = __floats2half2_rn(O1[2], O1[3]);
                *(__half2*)&outh[g * 64 + (c + 1) * 8 + 2 * tg]
                    = __floats2half2_rn(O2[0], O2[1]);
                *(__half2*)&outh[(g + 8) * 64 + (c + 1) * 8 + 2 * tg]
                    = __floats2half2_rn(O2[2], O2[3]);
            }
        }
        __syncthreads();                     // outh ready

        {
            uint2 val = *(uint2*)&outh[tid * 4];
            *(uint2*)(g_aoh + (size_t)pos * EDIM + tid * 4) = val;
        }
        __syncthreads();                     // stage s free
    }
}

// ---------------------------------------------------------------------------
// Launch
// ---------------------------------------------------------------------------
extern "C" void kernel_launch(void* const* d_in, const int* in_sizes, int n_in,
                              void* d_out, int out_size)
{
    const float* values    = (const float*)d_in[0];
    const float* keys      = (const float*)d_in[1];
    const float* queries   = (const float*)d_in[2];
    const int*   mask      = (const int*)  d_in[3];
    const float* condition = (const float*)d_in[4];
    const float* Wc        = (const float*)d_in[5];
    const float* bc        = (const float*)d_in[6];
    const float* Wo        = (const float*)d_in[7];
    const float* bo        = (const float*)d_in[8];
    float* out = (float*)d_out;

    float* cond_ptr;
    __half *ch, *wch, *woh, *aoh;
    cudaGetSymbolAddress((void**)&cond_ptr, g_cond);
    cudaGetSymbolAddress((void**)&ch,  g_ch);
    cudaGetSymbolAddress((void**)&wch, g_wch);
    cudaGetSymbolAddress((void**)&woh, g_woh);
    cudaGetSymbolAddress((void**)&aoh, g_aoh);

    cudaFuncSetAttribute(gemm_hmma,
                         cudaFuncAttributeMaxDynamicSharedMemorySize, DSMEM);

    // fused converts (one launch)
    {
        int ntot = N_COND + N_WC + N_WO;
        to_half_all<<<ntot / 4 / 256, 256>>>(condition, ch, Wc, wch, Wo, woh);
    }

    // 1) cond = condition @ Wc^T + bc : M=8192, N=1024, K=512
    {
        dim3 grid(EDIM / BN, (NBATCH * SQ) / BM);
        gemm_hmma<<<grid, 128, DSMEM>>>(ch, wch, bc, cond_ptr,
                                        NBATCH * SQ, EDIM, CDIM);
    }

    // 2) attention -> g_aoh (fp16), MMA per position
    attn_kernel<<<(NBATCH * SKV) / POS_PER_CTA, 256>>>(queries, keys, values, mask);

    // 3) out = attout @ Wo^T + bo : M=16384, N=1024, K=1024
    {
        dim3 grid(EDIM / BN, (NBATCH * SKV) / BM);
        gemm_hmma<<<grid, 128, DSMEM>>>(aoh, woh, bo, out,
                                        NBATCH * SKV, EDIM, EDIM);
    }
}